// round 4
// baseline (speedup 1.0000x reference)
#include <cuda_runtime.h>

// TemporalDecay: out = h + (1-m)*g*(h_fwd - h),
//   g = exp(-relu(delta*W + b)),  delta integer in [1,4],
//   h_fwd[b,t,j] = h_a[b, t-(delta-1), j]   (<= 3 rows back).
//
// R4: R3 structure (gamma table + 7-row register halo, fully unrolled) plus:
//  - float-domain delta selects (no F2I), gam[0] dropped  -> fewer regs
//  - __launch_bounds__(256,4): cap 64 regs -> 32 warps/SM (was 24)
//  - PDL: decay kernel launches while gamma kernel runs; it issues all
//    gamma-independent loads, then cudaGridDependencySynchronize(), then
//    reads the table. Hides the prologue-kernel latency.

static constexpr int Bq = 32, Tq = 2048;
static constexpr int C4 = 64;          // float4s per 256-channel row
static constexpr int SEG = 4;          // t rows per thread
static constexpr int NSEG = Tq / SEG;  // 512
static constexpr int THREADS = 256;
static constexpr int BLOCKS = Bq * C4 * NSEG / THREADS;  // 4096

// gamma[d-1][channel], 4 rows of 64 float4s (only rows 1..3 read by decay).
__device__ float4 g_gamma4[4 * C4];

__global__ void gamma_precompute_kernel(const float* __restrict__ W,
                                        const float* __restrict__ bias) {
    // Let dependent launch happen immediately; consumer gri-dep-syncs on our
    // full completion anyway.
    cudaTriggerProgrammaticLaunchCompletion();
    int j = threadIdx.x;  // 0..255 channel
    float w = W[j];
    float bb = bias[j];
    float* gf = (float*)g_gamma4;
#pragma unroll
    for (int dm = 0; dm < 4; dm++) {
        float x = fmaxf(fmaf((float)(dm + 1), w, bb), 0.0f);
        gf[dm * 256 + j] = __expf(-x);
    }
}

__global__ void __launch_bounds__(THREADS, 4) decay_kernel(
    const float4* __restrict__ H,      // h_a  [B*T*64] float4
    const float4* __restrict__ DL,     // deltas [B*T*16] float4
    const float4* __restrict__ MM,     // mask   [B*T*16] float4
    float4* __restrict__ OUT)
{
    const int g    = blockIdx.x * THREADS + threadIdx.x;
    const int col4 = g & 63;
    const int seg  = (g >> 6) & (NSEG - 1);
    const int bb   = g >> 15;
    const int t0   = seg * SEG;

    const int rb    = bb * Tq * C4 + col4;              // row base into H/OUT
    const int dbase = (bb * Tq + t0) * 16 + (col4 & 15);

    // --- gamma-independent loads first (overlap with gamma kernel via PDL) ---
    // R[k] holds row t0-3+k (k=0..2 halo, clamped; k=3..6 the 4 output rows).
    float4 R[7];
#pragma unroll
    for (int k = 0; k < 3; k++) {
        const int t = max(t0 - 3 + k, 0);   // clamped halo never selected at t0==0
        R[k] = __ldg(H + rb + t * C4);
    }
#pragma unroll
    for (int s = 0; s < SEG; s++)
        R[3 + s] = __ldg(H + rb + (t0 + s) * C4);

    float4 dl[SEG], mm[SEG];
#pragma unroll
    for (int s = 0; s < SEG; s++) {
        dl[s] = __ldg(DL + dbase + s * 16);
        mm[s] = __ldg(MM + dbase + s * 16);
    }

    // --- wait for gamma table, then load this thread's 3 float4s (L1-hot) ---
    cudaGridDependencySynchronize();
    float4 gam1 = __ldg(g_gamma4 + 1 * C4 + col4);
    float4 gam2 = __ldg(g_gamma4 + 2 * C4 + col4);
    float4 gam3 = __ldg(g_gamma4 + 3 * C4 + col4);

    // --- compute + store (float-domain selects; delta in {1,2,3,4}) ---
#pragma unroll
    for (int s = 0; s < SEG; s++) {
        const float4 ha = R[3 + s];
        const float4 w1 = R[2 + s];
        const float4 w2 = R[1 + s];
        const float4 w3 = R[0 + s];
        float4 o;
#define PROC(c)                                                           \
        {                                                                 \
            const float dv = dl[s].c;                                     \
            const float f  = (dv == 1.0f) ? ha.c                          \
                           : (dv == 2.0f) ? w1.c                          \
                           : (dv == 3.0f) ? w2.c : w3.c;                  \
            const float gv = (dv == 2.0f) ? gam1.c                        \
                           : (dv == 3.0f) ? gam2.c : gam3.c;              \
            /* dv==1 => f-ha==0, gv irrelevant */                         \
            o.c = fmaf((1.0f - mm[s].c) * gv, f - ha.c, ha.c);            \
        }
        PROC(x) PROC(y) PROC(z) PROC(w)
#undef PROC
        OUT[rb + (t0 + s) * C4] = o;
    }
}

extern "C" void kernel_launch(void* const* d_in, const int* in_sizes, int n_in,
                              void* d_out, int out_size) {
    const float4* h_a    = (const float4*)d_in[0];
    const float4* deltas = (const float4*)d_in[1];
    const float4* Mmask  = (const float4*)d_in[2];
    const float*  W      = (const float*)d_in[3];
    const float*  b      = (const float*)d_in[4];
    float4* out = (float4*)d_out;

    gamma_precompute_kernel<<<1, 256>>>(W, b);

    // PDL: decay launches/overlaps while gamma runs; decay grid-dep-syncs
    // before touching the table.
    cudaLaunchAttribute attr[1];
    attr[0].id = cudaLaunchAttributeProgrammaticStreamSerialization;
    attr[0].val.programmaticStreamSerializationAllowed = 1;
    cudaLaunchConfig_t cfg = {};
    cfg.gridDim = dim3(BLOCKS);
    cfg.blockDim = dim3(THREADS);
    cfg.dynamicSmemBytes = 0;
    cfg.stream = 0;
    cfg.attrs = attr;
    cfg.numAttrs = 1;
    cudaLaunchKernelEx(&cfg, decay_kernel, h_a, deltas, Mmask, out);
}

// round 5
// speedup vs baseline: 1.0536x; 1.0536x over previous
#include <cuda_runtime.h>

// TemporalDecay: out = h + (1-m)*g*(h_fwd - h),
//   g = exp(-relu(delta*W + b)),  delta integer in [1,4],
//   h_fwd[b,t,j] = h_a[b, t-(delta-1), j]   (<= 3 rows back).
//
// R5: R3's hot loop (gamma table + 7-row register halo, fully unrolled,
// NATURAL register allocation — R4's 64-reg cap caused spills and regressed)
// + PDL so the decay grid launches and issues its gamma-independent loads
// while the tiny gamma kernel runs, + float-domain delta selects (no F2I).

static constexpr int Bq = 32, Tq = 2048;
static constexpr int C4 = 64;          // float4s per 256-channel row
static constexpr int SEG = 4;          // t rows per thread
static constexpr int NSEG = Tq / SEG;  // 512
static constexpr int THREADS = 256;
static constexpr int BLOCKS = Bq * C4 * NSEG / THREADS;  // 4096

// gamma[d-1][channel], 4 rows of 64 float4s (only rows 1..3 read by decay).
__device__ float4 g_gamma4[4 * C4];

__global__ void gamma_precompute_kernel(const float* __restrict__ W,
                                        const float* __restrict__ bias) {
    // Allow the dependent decay grid to begin launching immediately; it does
    // cudaGridDependencySynchronize() (full completion of this grid) before
    // reading the table, so correctness is preserved.
    cudaTriggerProgrammaticLaunchCompletion();
    int j = threadIdx.x;  // 0..255 channel
    float w = W[j];
    float bb = bias[j];
    float* gf = (float*)g_gamma4;
#pragma unroll
    for (int dm = 0; dm < 4; dm++) {
        float x = fmaxf(fmaf((float)(dm + 1), w, bb), 0.0f);
        gf[dm * 256 + j] = __expf(-x);
    }
}

__global__ void __launch_bounds__(THREADS) decay_kernel(
    const float4* __restrict__ H,      // h_a  [B*T*64] float4
    const float4* __restrict__ DL,     // deltas [B*T*16] float4
    const float4* __restrict__ MM,     // mask   [B*T*16] float4
    float4* __restrict__ OUT)
{
    const int g    = blockIdx.x * THREADS + threadIdx.x;
    const int col4 = g & 63;
    const int seg  = (g >> 6) & (NSEG - 1);
    const int bb   = g >> 15;
    const int t0   = seg * SEG;

    const int rb    = bb * Tq * C4 + col4;              // row base into H/OUT
    const int dbase = (bb * Tq + t0) * 16 + (col4 & 15);

    // --- gamma-independent loads first (overlap with gamma kernel via PDL) ---
    // R[k] holds row t0-3+k (k=0..2 halo, clamped; k=3..6 the 4 output rows).
    float4 R[7];
#pragma unroll
    for (int k = 0; k < 3; k++) {
        const int t = max(t0 - 3 + k, 0);   // clamped halo never selected at t0==0
        R[k] = __ldg(H + rb + t * C4);
    }
#pragma unroll
    for (int s = 0; s < SEG; s++)
        R[3 + s] = __ldg(H + rb + (t0 + s) * C4);

    float4 dl[SEG], mm[SEG];
#pragma unroll
    for (int s = 0; s < SEG; s++) {
        dl[s] = __ldg(DL + dbase + s * 16);
        mm[s] = __ldg(MM + dbase + s * 16);
    }

    // --- wait for gamma table, then load this thread's 3 float4s (L1-hot) ---
    cudaGridDependencySynchronize();
    float4 gam1 = __ldg(g_gamma4 + 1 * C4 + col4);
    float4 gam2 = __ldg(g_gamma4 + 2 * C4 + col4);
    float4 gam3 = __ldg(g_gamma4 + 3 * C4 + col4);

    // --- compute + store (float-domain selects; delta in {1,2,3,4}) ---
#pragma unroll
    for (int s = 0; s < SEG; s++) {
        const float4 ha = R[3 + s];
        const float4 w1 = R[2 + s];
        const float4 w2 = R[1 + s];
        const float4 w3 = R[0 + s];
        float4 o;
#define PROC(c)                                                           \
        {                                                                 \
            const float dv = dl[s].c;                                     \
            const float f  = (dv == 1.0f) ? ha.c                          \
                           : (dv == 2.0f) ? w1.c                          \
                           : (dv == 3.0f) ? w2.c : w3.c;                  \
            const float gv = (dv == 2.0f) ? gam1.c                        \
                           : (dv == 3.0f) ? gam2.c : gam3.c;              \
            /* dv==1 => f-ha==0, gv irrelevant */                         \
            o.c = fmaf((1.0f - mm[s].c) * gv, f - ha.c, ha.c);            \
        }
        PROC(x) PROC(y) PROC(z) PROC(w)
#undef PROC
        OUT[rb + (t0 + s) * C4] = o;
    }
}

extern "C" void kernel_launch(void* const* d_in, const int* in_sizes, int n_in,
                              void* d_out, int out_size) {
    const float4* h_a    = (const float4*)d_in[0];
    const float4* deltas = (const float4*)d_in[1];
    const float4* Mmask  = (const float4*)d_in[2];
    const float*  W      = (const float*)d_in[3];
    const float*  b      = (const float*)d_in[4];
    float4* out = (float4*)d_out;

    gamma_precompute_kernel<<<1, 256>>>(W, b);

    // PDL: decay launches/overlaps while gamma runs; decay grid-dep-syncs
    // before touching the table.
    cudaLaunchAttribute attr[1];
    attr[0].id = cudaLaunchAttributeProgrammaticStreamSerialization;
    attr[0].val.programmaticStreamSerializationAllowed = 1;
    cudaLaunchConfig_t cfg = {};
    cfg.gridDim = dim3(BLOCKS);
    cfg.blockDim = dim3(THREADS);
    cfg.dynamicSmemBytes = 0;
    cfg.stream = 0;
    cfg.attrs = attr;
    cfg.numAttrs = 1;
    cudaLaunchKernelEx(&cfg, decay_kernel, h_a, deltas, Mmask, out);
}

// round 6
// speedup vs baseline: 1.1802x; 1.1201x over previous
#include <cuda_runtime.h>

// TemporalDecay: out = h + (1-m)*g*(h_fwd - h),
//   g = exp(-relu(delta*W + b)),  delta integer in [1,4],
//   h_fwd[b,t,j] = h_a[b, t-(delta-1), j]   (<= 3 rows back).
//
// R6: SEG=2 rows per thread -> live set ~48 floats, so a 64-reg cap
// (__launch_bounds__(256,4)) fits WITHOUT spilling (R4's cap failed because
// SEG=4 needs ~84 regs). 4 blocks/SM = 32 warps (vs 21) for latency hiding.
// Halo amplification (2.5x on H at L1/L2) is absorbed: halo lines are cache
// hits and DRAM-side traffic is unchanged. gamma table + PDL retained.

static constexpr int Bq = 32, Tq = 2048;
static constexpr int C4 = 64;          // float4s per 256-channel row
static constexpr int SEG = 2;          // t rows per thread
static constexpr int NSEG = Tq / SEG;  // 1024
static constexpr int THREADS = 256;
static constexpr int BLOCKS = Bq * C4 * NSEG / THREADS;  // 8192

// gamma[d-1][channel], 4 rows of 64 float4s (only rows 1..3 read by decay).
__device__ float4 g_gamma4[4 * C4];

__global__ void gamma_precompute_kernel(const float* __restrict__ W,
                                        const float* __restrict__ bias) {
    cudaTriggerProgrammaticLaunchCompletion();
    int j = threadIdx.x;  // 0..255 channel
    float w = W[j];
    float bb = bias[j];
    float* gf = (float*)g_gamma4;
#pragma unroll
    for (int dm = 0; dm < 4; dm++) {
        float x = fmaxf(fmaf((float)(dm + 1), w, bb), 0.0f);
        gf[dm * 256 + j] = __expf(-x);
    }
}

__global__ void __launch_bounds__(THREADS, 4) decay_kernel(
    const float4* __restrict__ H,      // h_a  [B*T*64] float4
    const float4* __restrict__ DL,     // deltas [B*T*16] float4
    const float4* __restrict__ MM,     // mask   [B*T*16] float4
    float4* __restrict__ OUT)
{
    const int g    = blockIdx.x * THREADS + threadIdx.x;
    const int col4 = g & 63;
    const int seg  = (g >> 6) & (NSEG - 1);
    const int bb   = g >> 16;
    const int t0   = seg * SEG;

    const int rb    = bb * Tq * C4 + col4;              // row base into H/OUT
    const int dbase = (bb * Tq + t0) * 16 + (col4 & 15);

    // --- gamma-independent loads first (overlap with gamma kernel via PDL) ---
    // R[k] holds row t0-3+k (k=0..2 halo, clamped; k=3..4 the 2 output rows).
    float4 R[5];
#pragma unroll
    for (int k = 0; k < 3; k++) {
        const int t = max(t0 - 3 + k, 0);   // clamped halo never selected at t0==0
        R[k] = __ldg(H + rb + t * C4);
    }
#pragma unroll
    for (int s = 0; s < SEG; s++)
        R[3 + s] = __ldg(H + rb + (t0 + s) * C4);

    float4 dl[SEG], mm[SEG];
#pragma unroll
    for (int s = 0; s < SEG; s++) {
        dl[s] = __ldg(DL + dbase + s * 16);
        mm[s] = __ldg(MM + dbase + s * 16);
    }

    // --- wait for gamma table, then load this thread's 3 float4s (L1-hot) ---
    cudaGridDependencySynchronize();
    const float4 gam1 = __ldg(g_gamma4 + 1 * C4 + col4);
    const float4 gam2 = __ldg(g_gamma4 + 2 * C4 + col4);
    const float4 gam3 = __ldg(g_gamma4 + 3 * C4 + col4);

    // --- compute + store (float-domain selects; delta in {1,2,3,4}) ---
#pragma unroll
    for (int s = 0; s < SEG; s++) {
        const float4 ha = R[3 + s];
        const float4 w1 = R[2 + s];
        const float4 w2 = R[1 + s];
        const float4 w3 = R[0 + s];
        float4 o;
#define PROC(c)                                                           \
        {                                                                 \
            const float dv = dl[s].c;                                     \
            const float f  = (dv == 1.0f) ? ha.c                          \
                           : (dv == 2.0f) ? w1.c                          \
                           : (dv == 3.0f) ? w2.c : w3.c;                  \
            const float gv = (dv == 2.0f) ? gam1.c                        \
                           : (dv == 3.0f) ? gam2.c : gam3.c;              \
            /* dv==1 => f-ha==0, gv irrelevant */                         \
            o.c = fmaf((1.0f - mm[s].c) * gv, f - ha.c, ha.c);            \
        }
        PROC(x) PROC(y) PROC(z) PROC(w)
#undef PROC
        OUT[rb + (t0 + s) * C4] = o;
    }
}

extern "C" void kernel_launch(void* const* d_in, const int* in_sizes, int n_in,
                              void* d_out, int out_size) {
    const float4* h_a    = (const float4*)d_in[0];
    const float4* deltas = (const float4*)d_in[1];
    const float4* Mmask  = (const float4*)d_in[2];
    const float*  W      = (const float*)d_in[3];
    const float*  b      = (const float*)d_in[4];
    float4* out = (float4*)d_out;

    gamma_precompute_kernel<<<1, 256>>>(W, b);

    // PDL: decay launches/overlaps while gamma runs; decay grid-dep-syncs
    // before touching the table.
    cudaLaunchAttribute attr[1];
    attr[0].id = cudaLaunchAttributeProgrammaticStreamSerialization;
    attr[0].val.programmaticStreamSerializationAllowed = 1;
    cudaLaunchConfig_t cfg = {};
    cfg.gridDim = dim3(BLOCKS);
    cfg.blockDim = dim3(THREADS);
    cfg.dynamicSmemBytes = 0;
    cfg.stream = 0;
    cfg.attrs = attr;
    cfg.numAttrs = 1;
    cudaLaunchKernelEx(&cfg, decay_kernel, h_a, deltas, Mmask, out);
}

// round 7
// speedup vs baseline: 1.1904x; 1.0087x over previous
#include <cuda_runtime.h>

// TemporalDecay: out = h + (1-m)*g*(h_fwd - h),
//   g = exp(-relu(delta*W + b)),  delta integer in [1,4],
//   h_fwd[b,t,j] = h_a[b, t-(delta-1), j]   (<= 3 rows back).
//
// R7: identical per-thread body to R6 (SEG=2, register halo, gamma table,
// PDL) but 128-thread blocks with __launch_bounds__(128, 9):
//   65536/(128*9) -> 56 regs, exactly R6's natural allocation, so no spill,
//   and 9 blocks * 4 warps = 36 warps/SM (56% occ) vs R6's 32-warp cap with
//   coarse 8-warp block granularity. 16384 small blocks also smooth the
//   work-steal tail.

static constexpr int Bq = 32, Tq = 2048;
static constexpr int C4 = 64;          // float4s per 256-channel row
static constexpr int SEG = 2;          // t rows per thread
static constexpr int NSEG = Tq / SEG;  // 1024
static constexpr int THREADS = 128;
static constexpr int BLOCKS = Bq * C4 * NSEG / THREADS;  // 16384

// gamma[d-1][channel], 4 rows of 64 float4s (only rows 1..3 read by decay).
__device__ float4 g_gamma4[4 * C4];

__global__ void gamma_precompute_kernel(const float* __restrict__ W,
                                        const float* __restrict__ bias) {
    cudaTriggerProgrammaticLaunchCompletion();
    int j = threadIdx.x;  // 0..255 channel
    float w = W[j];
    float bb = bias[j];
    float* gf = (float*)g_gamma4;
#pragma unroll
    for (int dm = 0; dm < 4; dm++) {
        float x = fmaxf(fmaf((float)(dm + 1), w, bb), 0.0f);
        gf[dm * 256 + j] = __expf(-x);
    }
}

__global__ void __launch_bounds__(THREADS, 9) decay_kernel(
    const float4* __restrict__ H,      // h_a  [B*T*64] float4
    const float4* __restrict__ DL,     // deltas [B*T*16] float4
    const float4* __restrict__ MM,     // mask   [B*T*16] float4
    float4* __restrict__ OUT)
{
    const int g    = blockIdx.x * THREADS + threadIdx.x;
    const int col4 = g & 63;
    const int seg  = (g >> 6) & (NSEG - 1);
    const int bb   = g >> 16;
    const int t0   = seg * SEG;

    const int rb    = bb * Tq * C4 + col4;              // row base into H/OUT
    const int dbase = (bb * Tq + t0) * 16 + (col4 & 15);

    // --- gamma-independent loads first (overlap with gamma kernel via PDL) ---
    // R[k] holds row t0-3+k (k=0..2 halo, clamped; k=3..4 the 2 output rows).
    float4 R[5];
#pragma unroll
    for (int k = 0; k < 3; k++) {
        const int t = max(t0 - 3 + k, 0);   // clamped halo never selected at t0==0
        R[k] = __ldg(H + rb + t * C4);
    }
#pragma unroll
    for (int s = 0; s < SEG; s++)
        R[3 + s] = __ldg(H + rb + (t0 + s) * C4);

    float4 dl[SEG], mm[SEG];
#pragma unroll
    for (int s = 0; s < SEG; s++) {
        dl[s] = __ldg(DL + dbase + s * 16);
        mm[s] = __ldg(MM + dbase + s * 16);
    }

    // --- wait for gamma table, then load this thread's 3 float4s (L1-hot) ---
    cudaGridDependencySynchronize();
    const float4 gam1 = __ldg(g_gamma4 + 1 * C4 + col4);
    const float4 gam2 = __ldg(g_gamma4 + 2 * C4 + col4);
    const float4 gam3 = __ldg(g_gamma4 + 3 * C4 + col4);

    // --- compute + store (float-domain selects; delta in {1,2,3,4}) ---
#pragma unroll
    for (int s = 0; s < SEG; s++) {
        const float4 ha = R[3 + s];
        const float4 w1 = R[2 + s];
        const float4 w2 = R[1 + s];
        const float4 w3 = R[0 + s];
        float4 o;
#define PROC(c)                                                           \
        {                                                                 \
            const float dv = dl[s].c;                                     \
            const float f  = (dv == 1.0f) ? ha.c                          \
                           : (dv == 2.0f) ? w1.c                          \
                           : (dv == 3.0f) ? w2.c : w3.c;                  \
            const float gv = (dv == 2.0f) ? gam1.c                        \
                           : (dv == 3.0f) ? gam2.c : gam3.c;              \
            /* dv==1 => f-ha==0, gv irrelevant */                         \
            o.c = fmaf((1.0f - mm[s].c) * gv, f - ha.c, ha.c);            \
        }
        PROC(x) PROC(y) PROC(z) PROC(w)
#undef PROC
        OUT[rb + (t0 + s) * C4] = o;
    }
}

extern "C" void kernel_launch(void* const* d_in, const int* in_sizes, int n_in,
                              void* d_out, int out_size) {
    const float4* h_a    = (const float4*)d_in[0];
    const float4* deltas = (const float4*)d_in[1];
    const float4* Mmask  = (const float4*)d_in[2];
    const float*  W      = (const float*)d_in[3];
    const float*  b      = (const float*)d_in[4];
    float4* out = (float4*)d_out;

    gamma_precompute_kernel<<<1, 256>>>(W, b);

    // PDL: decay launches/overlaps while gamma runs; decay grid-dep-syncs
    // before touching the table.
    cudaLaunchAttribute attr[1];
    attr[0].id = cudaLaunchAttributeProgrammaticStreamSerialization;
    attr[0].val.programmaticStreamSerializationAllowed = 1;
    cudaLaunchConfig_t cfg = {};
    cfg.gridDim = dim3(BLOCKS);
    cfg.blockDim = dim3(THREADS);
    cfg.dynamicSmemBytes = 0;
    cfg.stream = 0;
    cfg.attrs = attr;
    cfg.numAttrs = 1;
    cudaLaunchKernelEx(&cfg, decay_kernel, h_a, deltas, Mmask, out);
}